// round 14
// baseline (speedup 1.0000x reference)
#include <cuda_runtime.h>

// SpectralGatingNetwork: out = Re(IFFT( W .* FFT(x, axis=-1) ))
// Real-packing: z = x[b0] + i*x[b1], gate by conjugate-symmetric
// Weff[k] = 0.5*(W[k] + conj(W[(N-k)%N])) => y0 = Re, y1 = Im.
// Radix-8 Stockham, 64 threads/pair, 4 pairs (8 batches) per CTA, one CTA per (h,l).
// Packed f32x2 adds/subs; Chebyshev-recurrence twiddles; double-buffer ping-pong.
// ALL barriers are __syncthreads (1 HW barrier/CTA): named pair-barriers were
// consuming 5 HW barriers/CTA and capping residency at 4 CTAs/SM.

#define D 512
#define PAIRS_PER_BLOCK 4
#define THREADS (64 * PAIRS_PER_BLOCK)
#define SPAD 576

typedef unsigned long long u64t;

__device__ __forceinline__ u64t f2u(float2 a) {
    u64t r;
    asm("mov.b64 %0, {%1, %2};" : "=l"(r) : "f"(a.x), "f"(a.y));
    return r;
}
__device__ __forceinline__ float2 u2f(u64t v) {
    float2 r;
    asm("mov.b64 {%0, %1}, %2;" : "=f"(r.x), "=f"(r.y) : "l"(v));
    return r;
}

// packed complex add: one FADD2
__device__ __forceinline__ float2 cadd(float2 a, float2 b) {
    u64t r, x = f2u(a), y = f2u(b);
    asm("add.rn.f32x2 %0, %1, %2;" : "=l"(r) : "l"(x), "l"(y));
    return u2f(r);
}
// packed complex sub: a - b as fma(b, -1, a) -> one FFMA2
__device__ __forceinline__ float2 csub(float2 a, float2 b) {
    const u64t NEG1 = 0xBF800000BF800000ULL;
    u64t r, x = f2u(a), y = f2u(b);
    asm("fma.rn.f32x2 %0, %1, %2, %3;" : "=l"(r) : "l"(y), "l"(NEG1), "l"(x));
    return u2f(r);
}
__device__ __forceinline__ u64t fma2u(u64t a, u64t b, u64t c) {
    u64t r;
    asm("fma.rn.f32x2 %0, %1, %2, %3;" : "=l"(r) : "l"(a), "l"(b), "l"(c));
    return r;
}
__device__ __forceinline__ u64t neg2u(u64t a) {
    const u64t NEG1 = 0xBF800000BF800000ULL;
    u64t r;
    asm("mul.rn.f32x2 %0, %1, %2;" : "=l"(r) : "l"(a), "l"(NEG1));
    return r;
}

__device__ __forceinline__ float2 cmul(float2 a, float2 b) {
    return make_float2(fmaf(a.x, b.x, -a.y * b.y), fmaf(a.x, b.y, a.y * b.x));
}

// +-i butterflies folded into FADD sign modifiers
template <int S>
__device__ __forceinline__ void bfly_j(float2 e, float2 d, float2& lo, float2& hi) {
    if (S < 0) {
        lo = make_float2(e.x + d.y, e.y - d.x);
        hi = make_float2(e.x - d.y, e.y + d.x);
    } else {
        lo = make_float2(e.x - d.y, e.y + d.x);
        hi = make_float2(e.x + d.y, e.y - d.x);
    }
}

template <int S>
__device__ __forceinline__ void dft4(float2 x0, float2 x1, float2 x2, float2 x3, float2 o[4]) {
    float2 e0 = cadd(x0, x2), e1 = csub(x0, x2);
    float2 d0 = cadd(x1, x3), d1 = csub(x1, x3);
    o[0] = cadd(e0, d0);
    o[2] = csub(e0, d0);
    bfly_j<S>(e1, d1, o[1], o[3]);
}

template <int S>
__device__ __forceinline__ void dft8(const float2 a[8], float2 b[8]) {
    float2 e[4], o[4];
    dft4<S>(a[0], a[2], a[4], a[6], e);
    dft4<S>(a[1], a[3], a[5], a[7], o);
    const float r2 = 0.70710678118654752f;
    const float2 w1 = make_float2(r2, S * r2);
    const float2 w3 = make_float2(-r2, S * r2);
    float2 u1 = cmul(o[1], w1);
    float2 u3 = cmul(o[3], w3);
    b[0] = cadd(e[0], o[0]); b[4] = csub(e[0], o[0]);
    b[1] = cadd(e[1], u1);   b[5] = csub(e[1], u1);
    bfly_j<S>(e[2], o[2], b[2], b[6]);
    b[3] = cadd(e[3], u3);   b[7] = csub(e[3], u3);
}

// a[m] *= exp(S*i*two_pi_over_M*k*m) via Chebyshev recurrence (packed)
template <int S>
__device__ __forceinline__ void twiddle8(float2 a[8], int k, float two_pi_over_M) {
    float ang = (float)S * two_pi_over_M * (float)k;
    float s1, c1;
    __sincosf(ang, &s1, &c1);
    u64t W1 = f2u(make_float2(c1, s1));
    float tc = c1 + c1;
    u64t C = f2u(make_float2(tc, tc));
    const u64t NEGW0 = 0x00000000BF800000ULL;  // (-1.0f, 0.0f)
    u64t W2 = fma2u(W1, C, NEGW0);
    u64t nW1 = neg2u(W1);
    u64t W3 = fma2u(W2, C, nW1);
    u64t nW2 = neg2u(W2);
    u64t W4 = fma2u(W3, C, nW2);
    u64t nW3 = neg2u(W3);
    u64t W5 = fma2u(W4, C, nW3);
    u64t nW4 = neg2u(W4);
    u64t W6 = fma2u(W5, C, nW4);
    u64t nW5 = neg2u(W5);
    u64t W7 = fma2u(W6, C, nW5);
    a[1] = cmul(a[1], u2f(W1));
    a[2] = cmul(a[2], u2f(W2));
    a[3] = cmul(a[3], u2f(W3));
    a[4] = cmul(a[4], u2f(W4));
    a[5] = cmul(a[5], u2f(W5));
    a[6] = cmul(a[6], u2f(W6));
    a[7] = cmul(a[7], u2f(W7));
}

// Conflict-free for stores 8j+t / 72blk and loads j+64m; keeps 8j+t contiguous.
__device__ __forceinline__ int pad(int i) { return i + ((i >> 3) & ~1); }

__device__ __forceinline__ void store8_vec(float2* base, const float2 b[8]) {
    float4* p = reinterpret_cast<float4*>(base);
    p[0] = make_float4(b[0].x, b[0].y, b[1].x, b[1].y);
    p[1] = make_float4(b[2].x, b[2].y, b[3].x, b[3].y);
    p[2] = make_float4(b[4].x, b[4].y, b[5].x, b[5].y);
    p[3] = make_float4(b[6].x, b[6].y, b[7].x, b[7].y);
}

__global__ void __launch_bounds__(THREADS, 5)
sgn_fft_kernel(const float* __restrict__ x,
               const float2* __restrict__ w,
               float* __restrict__ out,
               int batch_stride)
{
    __shared__ float2 smA[PAIRS_PER_BLOCK][SPAD];
    __shared__ float2 smB[PAIRS_PER_BLOCK][SPAD];
    __shared__ float2 weff_sh[D];   // natural layout: weff_sh[k] = Weff[k]

    const int tid = threadIdx.x;
    const int r = tid >> 6;
    const int j = tid & 63;

    const int hl = blockIdx.x;
    const long long base = (long long)hl * D;
    const float2* __restrict__ wrow = w + base;

    // ---- Weff = (W[k] + conj(W[(512-k)&511])) * (1/1024)
#pragma unroll
    for (int k = tid; k < D; k += THREADS) {
        int kc = (D - k) & (D - 1);
        float2 wk = wrow[k];
        float2 wkc = wrow[kc];
        weff_sh[k] = make_float2((wk.x + wkc.x) * (1.0f / 1024.0f),
                                 (wk.y - wkc.y) * (1.0f / 1024.0f));
    }

    const float* __restrict__ x0 = x + base + (long long)(2 * r) * batch_stride;
    const float* __restrict__ x1 = x0 + batch_stride;
    float* __restrict__ o0 = out + base + (long long)(2 * r) * batch_stride;
    float* __restrict__ o1 = o0 + batch_stride;

    float2* bufA = smA[r];
    float2* bufB = smB[r];

    float2 a[8], b[8];

    // ------------- forward FFT of z = x0 + i*x1 -------------
#pragma unroll
    for (int m = 0; m < 8; m++) a[m] = make_float2(x0[j + 64 * m], x1[j + 64 * m]);
    dft8<-1>(a, b);
    store8_vec(&bufA[pad(8 * j)], b);
    __syncthreads();   // also covers weff_sh

    // stage 1 (L=8)
#pragma unroll
    for (int m = 0; m < 8; m++) a[m] = bufA[pad(j + 64 * m)];
    {
        int k = j & 7;
        twiddle8<-1>(a, k, 6.2831853071795865f / 64.0f);
        dft8<-1>(a, b);
        int blk = j >> 3;
#pragma unroll
        for (int t = 0; t < 8; t++) bufB[pad(blk * 64 + k + 8 * t)] = b[t];
    }
    __syncthreads();

    // stage 2 (L=64) -> Z[j+64t] in registers
#pragma unroll
    for (int m = 0; m < 8; m++) a[m] = bufB[pad(j + 64 * m)];
    twiddle8<-1>(a, j, 6.2831853071795865f / 512.0f);
    dft8<-1>(a, b);

    // ------------- spectral gating (natural layout, conflict-free) -------------
#pragma unroll
    for (int t = 0; t < 8; t++) {
        a[t] = cmul(weff_sh[j + 64 * t], b[t]);
    }

    // ------------- inverse FFT -------------
    // stage 0: write bufA (all pairs finished reading bufA before the last
    // CTA-wide barrier; bufB reads above are pair-internal and every thread
    // of each pair reads before any thread of that pair reaches the next
    // barrier, so the CTA-wide sync below covers the bufB write-after-read too)
    dft8<1>(a, b);
    store8_vec(&bufA[pad(8 * j)], b);
    __syncthreads();

#pragma unroll
    for (int m = 0; m < 8; m++) a[m] = bufA[pad(j + 64 * m)];
    {
        int k = j & 7;
        twiddle8<1>(a, k, 6.2831853071795865f / 64.0f);
        dft8<1>(a, b);
        int blk = j >> 3;
#pragma unroll
        for (int t = 0; t < 8; t++) bufB[pad(blk * 64 + k + 8 * t)] = b[t];
    }
    __syncthreads();

#pragma unroll
    for (int m = 0; m < 8; m++) a[m] = bufB[pad(j + 64 * m)];
    twiddle8<1>(a, j, 6.2831853071795865f / 512.0f);
    dft8<1>(a, b);
#pragma unroll
    for (int t = 0; t < 8; t++) {
        o0[j + 64 * t] = b[t].x;
        o1[j + 64 * t] = b[t].y;
    }
}

extern "C" void kernel_launch(void* const* d_in, const int* in_sizes, int n_in,
                              void* d_out, int out_size) {
    (void)n_in; (void)out_size;
    const float* x = (const float*)d_in[0];
    // d_in[1] = mask (unused)
    const float2* w = (const float2*)d_in[2];
    float* out = (float*)d_out;

    const int wrows = (in_sizes[2] / 2) / D;   // H*L = 16384
    const int batch_stride = wrows * D;

    sgn_fft_kernel<<<wrows, THREADS>>>(x, w, out, batch_stride);
}

// round 15
// speedup vs baseline: 1.0786x; 1.0786x over previous
#include <cuda_runtime.h>

// SpectralGatingNetwork: out = Re(IFFT( W .* FFT(x, axis=-1) ))
// Real-packing: z = x[b0] + i*x[b1], gate by conjugate-symmetric
// Weff[k] = 0.5*(W[k] + conj(W[(N-k)%N])) => y0 = Re, y1 = Im.
// Radix-8 Stockham, 64 threads/pair, 4 pairs (8 batches) per CTA, one CTA per (h,l).
// Packed f32x2 adds/subs; Chebyshev-recurrence twiddles; double-buffer ping-pong.
// R10 config (pair-local barriers, 4 CTAs/SM) — empirically optimal; R12-R14
// showed 5 CTAs/SM is reachable (via syncthreads-only) but strictly slower.
// New: Weff built via its own conjugate symmetry (halves W reads + init flops).

#define D 512
#define PAIRS_PER_BLOCK 4
#define THREADS (64 * PAIRS_PER_BLOCK)
#define SPAD 576

#define BAR_PAIR(id) asm volatile("bar.sync %0, 64;" :: "r"(id) : "memory")

typedef unsigned long long u64t;

__device__ __forceinline__ u64t f2u(float2 a) {
    u64t r;
    asm("mov.b64 %0, {%1, %2};" : "=l"(r) : "f"(a.x), "f"(a.y));
    return r;
}
__device__ __forceinline__ float2 u2f(u64t v) {
    float2 r;
    asm("mov.b64 {%0, %1}, %2;" : "=f"(r.x), "=f"(r.y) : "l"(v));
    return r;
}

// packed complex add: one FADD2
__device__ __forceinline__ float2 cadd(float2 a, float2 b) {
    u64t r, x = f2u(a), y = f2u(b);
    asm("add.rn.f32x2 %0, %1, %2;" : "=l"(r) : "l"(x), "l"(y));
    return u2f(r);
}
// packed complex sub: a - b as fma(b, -1, a) -> one FFMA2
__device__ __forceinline__ float2 csub(float2 a, float2 b) {
    const u64t NEG1 = 0xBF800000BF800000ULL;
    u64t r, x = f2u(a), y = f2u(b);
    asm("fma.rn.f32x2 %0, %1, %2, %3;" : "=l"(r) : "l"(y), "l"(NEG1), "l"(x));
    return u2f(r);
}
__device__ __forceinline__ u64t fma2u(u64t a, u64t b, u64t c) {
    u64t r;
    asm("fma.rn.f32x2 %0, %1, %2, %3;" : "=l"(r) : "l"(a), "l"(b), "l"(c));
    return r;
}
__device__ __forceinline__ u64t neg2u(u64t a) {
    const u64t NEG1 = 0xBF800000BF800000ULL;
    u64t r;
    asm("mul.rn.f32x2 %0, %1, %2;" : "=l"(r) : "l"(a), "l"(NEG1));
    return r;
}

__device__ __forceinline__ float2 cmul(float2 a, float2 b) {
    return make_float2(fmaf(a.x, b.x, -a.y * b.y), fmaf(a.x, b.y, a.y * b.x));
}

// +-i butterflies folded into FADD sign modifiers
template <int S>
__device__ __forceinline__ void bfly_j(float2 e, float2 d, float2& lo, float2& hi) {
    if (S < 0) {
        lo = make_float2(e.x + d.y, e.y - d.x);
        hi = make_float2(e.x - d.y, e.y + d.x);
    } else {
        lo = make_float2(e.x - d.y, e.y + d.x);
        hi = make_float2(e.x + d.y, e.y - d.x);
    }
}

template <int S>
__device__ __forceinline__ void dft4(float2 x0, float2 x1, float2 x2, float2 x3, float2 o[4]) {
    float2 e0 = cadd(x0, x2), e1 = csub(x0, x2);
    float2 d0 = cadd(x1, x3), d1 = csub(x1, x3);
    o[0] = cadd(e0, d0);
    o[2] = csub(e0, d0);
    bfly_j<S>(e1, d1, o[1], o[3]);
}

template <int S>
__device__ __forceinline__ void dft8(const float2 a[8], float2 b[8]) {
    float2 e[4], o[4];
    dft4<S>(a[0], a[2], a[4], a[6], e);
    dft4<S>(a[1], a[3], a[5], a[7], o);
    const float r2 = 0.70710678118654752f;
    const float2 w1 = make_float2(r2, S * r2);
    const float2 w3 = make_float2(-r2, S * r2);
    float2 u1 = cmul(o[1], w1);
    float2 u3 = cmul(o[3], w3);
    b[0] = cadd(e[0], o[0]); b[4] = csub(e[0], o[0]);
    b[1] = cadd(e[1], u1);   b[5] = csub(e[1], u1);
    bfly_j<S>(e[2], o[2], b[2], b[6]);
    b[3] = cadd(e[3], u3);   b[7] = csub(e[3], u3);
}

// a[m] *= exp(S*i*two_pi_over_M*k*m) via Chebyshev recurrence (packed):
// W_{m+1} = 2cos(theta)*W_m - W_{m-1}
template <int S>
__device__ __forceinline__ void twiddle8(float2 a[8], int k, float two_pi_over_M) {
    float ang = (float)S * two_pi_over_M * (float)k;
    float s1, c1;
    __sincosf(ang, &s1, &c1);
    u64t W1 = f2u(make_float2(c1, s1));
    float tc = c1 + c1;
    u64t C = f2u(make_float2(tc, tc));
    const u64t NEGW0 = 0x00000000BF800000ULL;  // (-1.0f, 0.0f)
    u64t W2 = fma2u(W1, C, NEGW0);
    u64t nW1 = neg2u(W1);
    u64t W3 = fma2u(W2, C, nW1);
    u64t nW2 = neg2u(W2);
    u64t W4 = fma2u(W3, C, nW2);
    u64t nW3 = neg2u(W3);
    u64t W5 = fma2u(W4, C, nW3);
    u64t nW4 = neg2u(W4);
    u64t W6 = fma2u(W5, C, nW4);
    u64t nW5 = neg2u(W5);
    u64t W7 = fma2u(W6, C, nW5);
    a[1] = cmul(a[1], u2f(W1));
    a[2] = cmul(a[2], u2f(W2));
    a[3] = cmul(a[3], u2f(W3));
    a[4] = cmul(a[4], u2f(W4));
    a[5] = cmul(a[5], u2f(W5));
    a[6] = cmul(a[6], u2f(W6));
    a[7] = cmul(a[7], u2f(W7));
}

// Conflict-free for stores 8j+t / 72blk and loads j+64m; keeps 8j+t contiguous.
__device__ __forceinline__ int pad(int i) { return i + ((i >> 3) & ~1); }

__device__ __forceinline__ void store8_vec(float2* base, const float2 b[8]) {
    float4* p = reinterpret_cast<float4*>(base);
    p[0] = make_float4(b[0].x, b[0].y, b[1].x, b[1].y);
    p[1] = make_float4(b[2].x, b[2].y, b[3].x, b[3].y);
    p[2] = make_float4(b[4].x, b[4].y, b[5].x, b[5].y);
    p[3] = make_float4(b[6].x, b[6].y, b[7].x, b[7].y);
}

__global__ void __launch_bounds__(THREADS, 4)
sgn_fft_kernel(const float* __restrict__ x,
               const float2* __restrict__ w,
               float* __restrict__ out,
               int batch_stride)
{
    __shared__ float2 smA[PAIRS_PER_BLOCK][SPAD];
    __shared__ float2 smB[PAIRS_PER_BLOCK][SPAD];
    __shared__ float2 weff_sh[D];   // natural layout: weff_sh[k] = Weff[k]

    const int tid = threadIdx.x;
    const int r = tid >> 6;
    const int j = tid & 63;
    const int barid = r + 1;

    const int hl = blockIdx.x;
    const long long base = (long long)hl * D;
    const float2* __restrict__ wrow = w + base;

    // ---- Weff = (W[k] + conj(W[(512-k)&511])) * (1/1024)
    // Weff is itself conjugate-symmetric: Weff[(512-k)&511] = conj(Weff[k]),
    // so one (wk, wkc) pair produces BOTH entries (halves W reads + flops).
    for (int k = tid; k <= D / 2; k += THREADS) {
        int kc = (D - k) & (D - 1);
        float2 wk = wrow[k];
        float2 wkc = wrow[kc];
        float ex = (wk.x + wkc.x) * (1.0f / 1024.0f);
        float ey = (wk.y - wkc.y) * (1.0f / 1024.0f);
        weff_sh[k]  = make_float2(ex, ey);
        weff_sh[kc] = make_float2(ex, -ey);
    }

    const float* __restrict__ x0 = x + base + (long long)(2 * r) * batch_stride;
    const float* __restrict__ x1 = x0 + batch_stride;
    float* __restrict__ o0 = out + base + (long long)(2 * r) * batch_stride;
    float* __restrict__ o1 = o0 + batch_stride;

    float2* bufA = smA[r];
    float2* bufB = smB[r];

    float2 a[8], b[8];

    // ------------- forward FFT of z = x0 + i*x1 -------------
#pragma unroll
    for (int m = 0; m < 8; m++) a[m] = make_float2(x0[j + 64 * m], x1[j + 64 * m]);
    dft8<-1>(a, b);
    store8_vec(&bufA[pad(8 * j)], b);
    __syncthreads();   // CTA-wide: also covers weff_sh

    // stage 1 (L=8)
#pragma unroll
    for (int m = 0; m < 8; m++) a[m] = bufA[pad(j + 64 * m)];
    {
        int k = j & 7;
        twiddle8<-1>(a, k, 6.2831853071795865f / 64.0f);
        dft8<-1>(a, b);
        int blk = j >> 3;
#pragma unroll
        for (int t = 0; t < 8; t++) bufB[pad(blk * 64 + k + 8 * t)] = b[t];
    }
    BAR_PAIR(barid);

    // stage 2 (L=64) -> Z[j+64t] in registers
#pragma unroll
    for (int m = 0; m < 8; m++) a[m] = bufB[pad(j + 64 * m)];
    twiddle8<-1>(a, j, 6.2831853071795865f / 512.0f);
    dft8<-1>(a, b);

    // ------------- spectral gating (natural layout, conflict-free) -------------
#pragma unroll
    for (int t = 0; t < 8; t++) {
        a[t] = cmul(weff_sh[j + 64 * t], b[t]);
    }

    // ------------- inverse FFT -------------
    dft8<1>(a, b);
    store8_vec(&bufA[pad(8 * j)], b);
    BAR_PAIR(barid);

#pragma unroll
    for (int m = 0; m < 8; m++) a[m] = bufA[pad(j + 64 * m)];
    {
        int k = j & 7;
        twiddle8<1>(a, k, 6.2831853071795865f / 64.0f);
        dft8<1>(a, b);
        int blk = j >> 3;
#pragma unroll
        for (int t = 0; t < 8; t++) bufB[pad(blk * 64 + k + 8 * t)] = b[t];
    }
    BAR_PAIR(barid);

#pragma unroll
    for (int m = 0; m < 8; m++) a[m] = bufB[pad(j + 64 * m)];
    twiddle8<1>(a, j, 6.2831853071795865f / 512.0f);
    dft8<1>(a, b);
#pragma unroll
    for (int t = 0; t < 8; t++) {
        o0[j + 64 * t] = b[t].x;
        o1[j + 64 * t] = b[t].y;
    }
}

extern "C" void kernel_launch(void* const* d_in, const int* in_sizes, int n_in,
                              void* d_out, int out_size) {
    (void)n_in; (void)out_size;
    const float* x = (const float*)d_in[0];
    // d_in[1] = mask (unused)
    const float2* w = (const float2*)d_in[2];
    float* out = (float*)d_out;

    const int wrows = (in_sizes[2] / 2) / D;   // H*L = 16384
    const int batch_stride = wrows * D;

    sgn_fft_kernel<<<wrows, THREADS>>>(x, w, out, batch_stride);
}

// round 16
// speedup vs baseline: 1.1806x; 1.0945x over previous
#include <cuda_runtime.h>

// SpectralGatingNetwork: out = Re(IFFT( W .* FFT(x, axis=-1) ))
// Real-packing: z = x[b0] + i*x[b1], gate by conjugate-symmetric
// Weff[k] = 0.5*(W[k] + conj(W[(N-k)%N])) => y0 = Re, y1 = Im.
// Radix-8 Stockham, 64 threads/pair, 4 pairs (8 batches) per CTA, one CTA per (h,l).
// Packed f32x2 adds/subs; Chebyshev-recurrence twiddles (packed).
// Exact R10 configuration — empirically optimal (R12-R15 perturbations all regressed):
// double-buffer ping-pong, 3 pair-local barriers + 1 syncthreads, 4 CTAs/SM.

#define D 512
#define PAIRS_PER_BLOCK 4
#define THREADS (64 * PAIRS_PER_BLOCK)
#define SPAD 576

#define BAR_PAIR(id) asm volatile("bar.sync %0, 64;" :: "r"(id) : "memory")

typedef unsigned long long u64t;

__device__ __forceinline__ u64t f2u(float2 a) {
    u64t r;
    asm("mov.b64 %0, {%1, %2};" : "=l"(r) : "f"(a.x), "f"(a.y));
    return r;
}
__device__ __forceinline__ float2 u2f(u64t v) {
    float2 r;
    asm("mov.b64 {%0, %1}, %2;" : "=f"(r.x), "=f"(r.y) : "l"(v));
    return r;
}

// packed complex add: one FADD2
__device__ __forceinline__ float2 cadd(float2 a, float2 b) {
    u64t r, x = f2u(a), y = f2u(b);
    asm("add.rn.f32x2 %0, %1, %2;" : "=l"(r) : "l"(x), "l"(y));
    return u2f(r);
}
// packed complex sub: a - b as fma(b, -1, a) -> one FFMA2
__device__ __forceinline__ float2 csub(float2 a, float2 b) {
    const u64t NEG1 = 0xBF800000BF800000ULL;
    u64t r, x = f2u(a), y = f2u(b);
    asm("fma.rn.f32x2 %0, %1, %2, %3;" : "=l"(r) : "l"(y), "l"(NEG1), "l"(x));
    return u2f(r);
}
// packed u64 helpers for the twiddle recurrence
__device__ __forceinline__ u64t fma2u(u64t a, u64t b, u64t c) {
    u64t r;
    asm("fma.rn.f32x2 %0, %1, %2, %3;" : "=l"(r) : "l"(a), "l"(b), "l"(c));
    return r;
}
__device__ __forceinline__ u64t neg2u(u64t a) {
    const u64t NEG1 = 0xBF800000BF800000ULL;
    u64t r;
    asm("mul.rn.f32x2 %0, %1, %2;" : "=l"(r) : "l"(a), "l"(NEG1));
    return r;
}

__device__ __forceinline__ float2 cmul(float2 a, float2 b) {
    return make_float2(fmaf(a.x, b.x, -a.y * b.y), fmaf(a.x, b.y, a.y * b.x));
}

// +-i butterflies folded into FADD sign modifiers
template <int S>
__device__ __forceinline__ void bfly_j(float2 e, float2 d, float2& lo, float2& hi) {
    if (S < 0) {
        lo = make_float2(e.x + d.y, e.y - d.x);
        hi = make_float2(e.x - d.y, e.y + d.x);
    } else {
        lo = make_float2(e.x - d.y, e.y + d.x);
        hi = make_float2(e.x + d.y, e.y - d.x);
    }
}

template <int S>
__device__ __forceinline__ void dft4(float2 x0, float2 x1, float2 x2, float2 x3, float2 o[4]) {
    float2 e0 = cadd(x0, x2), e1 = csub(x0, x2);
    float2 d0 = cadd(x1, x3), d1 = csub(x1, x3);
    o[0] = cadd(e0, d0);
    o[2] = csub(e0, d0);
    bfly_j<S>(e1, d1, o[1], o[3]);
}

template <int S>
__device__ __forceinline__ void dft8(const float2 a[8], float2 b[8]) {
    float2 e[4], o[4];
    dft4<S>(a[0], a[2], a[4], a[6], e);
    dft4<S>(a[1], a[3], a[5], a[7], o);
    const float r2 = 0.70710678118654752f;
    const float2 w1 = make_float2(r2, S * r2);
    const float2 w3 = make_float2(-r2, S * r2);
    float2 u1 = cmul(o[1], w1);
    float2 u3 = cmul(o[3], w3);
    b[0] = cadd(e[0], o[0]); b[4] = csub(e[0], o[0]);
    b[1] = cadd(e[1], u1);   b[5] = csub(e[1], u1);
    bfly_j<S>(e[2], o[2], b[2], b[6]);
    b[3] = cadd(e[3], u3);   b[7] = csub(e[3], u3);
}

// a[m] *= exp(S*i*two_pi_over_M*k*m) via Chebyshev recurrence on packed pairs:
// W_{m+1} = 2cos(theta)*W_m - W_{m-1}, W_0=(1,0), W_1=(cos,sin)
template <int S>
__device__ __forceinline__ void twiddle8(float2 a[8], int k, float two_pi_over_M) {
    float ang = (float)S * two_pi_over_M * (float)k;
    float s1, c1;
    __sincosf(ang, &s1, &c1);
    u64t W1 = f2u(make_float2(c1, s1));
    float tc = c1 + c1;
    u64t C = f2u(make_float2(tc, tc));
    const u64t NEGW0 = 0x00000000BF800000ULL;  // (-1.0f, 0.0f)
    u64t W2 = fma2u(W1, C, NEGW0);
    u64t nW1 = neg2u(W1);
    u64t W3 = fma2u(W2, C, nW1);
    u64t nW2 = neg2u(W2);
    u64t W4 = fma2u(W3, C, nW2);
    u64t nW3 = neg2u(W3);
    u64t W5 = fma2u(W4, C, nW3);
    u64t nW4 = neg2u(W4);
    u64t W6 = fma2u(W5, C, nW4);
    u64t nW5 = neg2u(W5);
    u64t W7 = fma2u(W6, C, nW5);
    a[1] = cmul(a[1], u2f(W1));
    a[2] = cmul(a[2], u2f(W2));
    a[3] = cmul(a[3], u2f(W3));
    a[4] = cmul(a[4], u2f(W4));
    a[5] = cmul(a[5], u2f(W5));
    a[6] = cmul(a[6], u2f(W6));
    a[7] = cmul(a[7], u2f(W7));
}

// Conflict-free for stores 8j+t / 72blk and loads j+64m; keeps 8j+t contiguous.
__device__ __forceinline__ int pad(int i) { return i + ((i >> 3) & ~1); }

__device__ __forceinline__ void store8_vec(float2* base, const float2 b[8]) {
    float4* p = reinterpret_cast<float4*>(base);
    p[0] = make_float4(b[0].x, b[0].y, b[1].x, b[1].y);
    p[1] = make_float4(b[2].x, b[2].y, b[3].x, b[3].y);
    p[2] = make_float4(b[4].x, b[4].y, b[5].x, b[5].y);
    p[3] = make_float4(b[6].x, b[6].y, b[7].x, b[7].y);
}

__global__ void __launch_bounds__(THREADS, 4)
sgn_fft_kernel(const float* __restrict__ x,
               const float2* __restrict__ w,
               float* __restrict__ out,
               int batch_stride)
{
    __shared__ float2 smA[PAIRS_PER_BLOCK][SPAD];
    __shared__ float2 smB[PAIRS_PER_BLOCK][SPAD];
    __shared__ float2 weff_sh[D];   // natural layout: weff_sh[k] = Weff[k]

    const int tid = threadIdx.x;
    const int r = tid >> 6;
    const int j = tid & 63;
    const int barid = r + 1;

    const int hl = blockIdx.x;
    const long long base = (long long)hl * D;
    const float2* __restrict__ wrow = w + base;

    // ---- Weff = (W[k] + conj(W[(512-k)&511])) * (1/1024)
#pragma unroll
    for (int k = tid; k < D; k += THREADS) {
        int kc = (D - k) & (D - 1);
        float2 wk = wrow[k];
        float2 wkc = wrow[kc];
        weff_sh[k] = make_float2((wk.x + wkc.x) * (1.0f / 1024.0f),
                                 (wk.y - wkc.y) * (1.0f / 1024.0f));
    }

    const float* __restrict__ x0 = x + base + (long long)(2 * r) * batch_stride;
    const float* __restrict__ x1 = x0 + batch_stride;
    float* __restrict__ o0 = out + base + (long long)(2 * r) * batch_stride;
    float* __restrict__ o1 = o0 + batch_stride;

    float2* bufA = smA[r];
    float2* bufB = smB[r];

    float2 a[8], b[8];

    // ------------- forward FFT of z = x0 + i*x1 -------------
#pragma unroll
    for (int m = 0; m < 8; m++) a[m] = make_float2(x0[j + 64 * m], x1[j + 64 * m]);
    dft8<-1>(a, b);
    store8_vec(&bufA[pad(8 * j)], b);
    __syncthreads();   // CTA-wide: also covers weff_sh

    // stage 1 (L=8)
#pragma unroll
    for (int m = 0; m < 8; m++) a[m] = bufA[pad(j + 64 * m)];
    {
        int k = j & 7;
        twiddle8<-1>(a, k, 6.2831853071795865f / 64.0f);
        dft8<-1>(a, b);
        int blk = j >> 3;
#pragma unroll
        for (int t = 0; t < 8; t++) bufB[pad(blk * 64 + k + 8 * t)] = b[t];
    }
    BAR_PAIR(barid);

    // stage 2 (L=64) -> Z[j+64t] in registers
#pragma unroll
    for (int m = 0; m < 8; m++) a[m] = bufB[pad(j + 64 * m)];
    twiddle8<-1>(a, j, 6.2831853071795865f / 512.0f);
    dft8<-1>(a, b);

    // ------------- spectral gating (natural layout, conflict-free) -------------
#pragma unroll
    for (int t = 0; t < 8; t++) {
        a[t] = cmul(weff_sh[j + 64 * t], b[t]);
    }

    // ------------- inverse FFT -------------
    dft8<1>(a, b);
    store8_vec(&bufA[pad(8 * j)], b);
    BAR_PAIR(barid);

#pragma unroll
    for (int m = 0; m < 8; m++) a[m] = bufA[pad(j + 64 * m)];
    {
        int k = j & 7;
        twiddle8<1>(a, k, 6.2831853071795865f / 64.0f);
        dft8<1>(a, b);
        int blk = j >> 3;
#pragma unroll
        for (int t = 0; t < 8; t++) bufB[pad(blk * 64 + k + 8 * t)] = b[t];
    }
    BAR_PAIR(barid);

#pragma unroll
    for (int m = 0; m < 8; m++) a[m] = bufB[pad(j + 64 * m)];
    twiddle8<1>(a, j, 6.2831853071795865f / 512.0f);
    dft8<1>(a, b);
#pragma unroll
    for (int t = 0; t < 8; t++) {
        o0[j + 64 * t] = b[t].x;
        o1[j + 64 * t] = b[t].y;
    }
}

extern "C" void kernel_launch(void* const* d_in, const int* in_sizes, int n_in,
                              void* d_out, int out_size) {
    (void)n_in; (void)out_size;
    const float* x = (const float*)d_in[0];
    // d_in[1] = mask (unused)
    const float2* w = (const float2*)d_in[2];
    float* out = (float*)d_out;

    const int wrows = (in_sizes[2] / 2) / D;   // H*L = 16384
    const int batch_stride = wrows * D;

    sgn_fft_kernel<<<wrows, THREADS>>>(x, w, out, batch_stride);
}